// round 16
// baseline (speedup 1.0000x reference)
#include <cuda_runtime.h>

#define N_TOK 4096
#define CDIM  256

// storage: raw bits (u16 = bf16, u8 = e4m3)
__device__ __align__(16) unsigned short g_xnb [2 * N_TOK * CDIM];
__device__ __align__(16) unsigned char  g_q8  [2 * N_TOK * CDIM];   // q, e4m3, prescaled
__device__ __align__(16) unsigned char  g_k8  [2 * N_TOK * CDIM];   // k, e4m3
__device__ __align__(16) unsigned short g_vb  [2 * N_TOK * CDIM];   // v, bf16
__device__ __align__(16) unsigned short g_attb[2 * N_TOK * CDIM];
__device__ __align__(16) unsigned short g_wqkvb[3 * CDIM * CDIM];
__device__ __align__(16) unsigned short g_wprojb[CDIM * CDIM];
// split-K attention partials (fp32, un-normalized)
__device__ __align__(16) float g_opart[2 * 2 * N_TOK * CDIM];
__device__ __align__(16) float g_lpart[2 * 2 * 8 * N_TOK];

#define QSC (0.17677669529663689f * 1.4426950408889634f)

__device__ __forceinline__ float ex2f(float x) {
    float y;
    asm("ex2.approx.ftz.f32 %0, %1;" : "=f"(y) : "f"(x));
    return y;
}
__device__ __forceinline__ unsigned s2u(const void* p) {
    return (unsigned)__cvta_generic_to_shared(p);
}
__device__ __forceinline__ void ldsm4(unsigned& r0, unsigned& r1, unsigned& r2, unsigned& r3, unsigned a) {
    asm volatile("ldmatrix.sync.aligned.m8n8.x4.shared.b16 {%0,%1,%2,%3}, [%4];" : "=r"(r0), "=r"(r1), "=r"(r2), "=r"(r3) : "r"(a));
}
__device__ __forceinline__ void ldsm4t(unsigned& r0, unsigned& r1, unsigned& r2, unsigned& r3, unsigned a) {
    asm volatile("ldmatrix.sync.aligned.m8n8.x4.trans.shared.b16 {%0,%1,%2,%3}, [%4];" : "=r"(r0), "=r"(r1), "=r"(r2), "=r"(r3) : "r"(a));
}
__device__ __forceinline__ void mma16816(float* c, const unsigned* a, unsigned b0, unsigned b1) {
    asm volatile("mma.sync.aligned.m16n8k16.row.col.f32.bf16.bf16.f32 {%0,%1,%2,%3},{%4,%5,%6,%7},{%8,%9},{%0,%1,%2,%3};" : "+f"(c[0]), "+f"(c[1]), "+f"(c[2]), "+f"(c[3]) : "r"(a[0]), "r"(a[1]), "r"(a[2]), "r"(a[3]), "r"(b0), "r"(b1));
}
__device__ __forceinline__ void mma16832q(float* c, const unsigned* a, unsigned b0, unsigned b1) {
    asm volatile("mma.sync.aligned.m16n8k32.row.col.f32.e4m3.e4m3.f32 {%0,%1,%2,%3},{%4,%5,%6,%7},{%8,%9},{%0,%1,%2,%3};" : "+f"(c[0]), "+f"(c[1]), "+f"(c[2]), "+f"(c[3]) : "r"(a[0]), "r"(a[1]), "r"(a[2]), "r"(a[3]), "r"(b0), "r"(b1));
}
__device__ __forceinline__ unsigned pack_bf(float lo, float hi) {
    unsigned r;
    asm("cvt.rn.bf16x2.f32 %0, %1, %2;" : "=r"(r) : "f"(hi), "f"(lo));
    return r;
}
__device__ __forceinline__ unsigned short pack_e4(float lo, float hi) {
    unsigned short r;
    asm("cvt.rn.satfinite.e4m3x2.f32 %0, %1, %2;" : "=h"(r) : "f"(hi), "f"(lo));
    return r;
}

// Kernel 0: weight conversion fp32 -> packed bf16 pairs
__global__ __launch_bounds__(256) void convw_kernel(const float* __restrict__ qw, const float* __restrict__ pw)
{
    int i = blockIdx.x * 256 + threadIdx.x;
    if (i < 98304) {
        ((unsigned*)g_wqkvb)[i] = pack_bf(qw[2 * i], qw[2 * i + 1]);
    } else {
        int j = i - 98304;
        ((unsigned*)g_wprojb)[j] = pack_bf(pw[2 * j], pw[2 * j + 1]);
    }
}

// Kernel 1: LayerNorm + (B,C,N)->(B,N,C) transpose, bf16 out
__global__ __launch_bounds__(256) void ln_kernel(const float* __restrict__ x, const float* __restrict__ nw, const float* __restrict__ nb)
{
    __shared__ float ts[CDIM][33];
    int tid = threadIdx.x;
    int bb = blockIdx.x >> 7;
    int n0 = (blockIdx.x & 127) * 32;

    int j = tid & 31;
    for (int c = tid >> 5; c < CDIM; c += 8) {
        ts[c][j] = x[(size_t)(bb * CDIM + c) * N_TOK + n0 + j];
    }
    __syncthreads();

    int jt = tid >> 3;
    int g = tid & 7;
    float sum = 0.f;
    float sq = 0.f;
    #pragma unroll
    for (int c0 = 0; c0 < CDIM; c0 += 8) {
        float v = ts[c0 + g][jt];
        sum += v;
        sq += v * v;
    }
    #pragma unroll
    for (int mm = 1; mm < 8; mm <<= 1) {
        sum += __shfl_xor_sync(0xffffffffu, sum, mm);
        sq  += __shfl_xor_sync(0xffffffffu, sq, mm);
    }
    float mean = sum * (1.f / CDIM);
    float var = sq * (1.f / CDIM) - mean * mean;
    float rstd = rsqrtf(var + 1e-5f);

    unsigned short* orow = g_xnb + (size_t)(bb * N_TOK + n0 + jt) * CDIM;
    #pragma unroll
    for (int i = 0; i < 8; i++) {
        int c = g * 32 + i * 4;
        float4 w4 = *(const float4*)(nw + c);
        float4 b4 = *(const float4*)(nb + c);
        float o0 = (ts[c + 0][jt] - mean) * rstd * w4.x + b4.x;
        float o1 = (ts[c + 1][jt] - mean) * rstd * w4.y + b4.y;
        float o2 = (ts[c + 2][jt] - mean) * rstd * w4.z + b4.z;
        float o3 = (ts[c + 3][jt] - mean) * rstd * w4.w + b4.w;
        uint2 pk;
        pk.x = pack_bf(o0, o1);
        pk.y = pack_bf(o2, o3);
        *(uint2*)(orow + c) = pk;
    }
}

// Kernel 2: QKV GEMM bf16 + bias; epilogue emits q,k as e4m3 (q prescaled), v as bf16
__global__ __launch_bounds__(256) void qkv_gemm_kernel(const float* __restrict__ bias)
{
    __shared__ __align__(16) unsigned short As[2][128][40];
    __shared__ __align__(16) unsigned short Bs[2][64][40];
    int tid = threadIdx.x;
    int li = tid & 31;
    int wp = tid >> 5;
    int m0 = blockIdx.x * 128;
    int j0 = blockIdx.y * 64;
    int wm = (wp >> 1) * 32;
    int wn = (wp & 1) * 32;
    float c[2][4][4];
    #pragma unroll
    for (int a1 = 0; a1 < 2; a1++) {
        #pragma unroll
        for (int a2 = 0; a2 < 4; a2++) {
            #pragma unroll
            for (int a3 = 0; a3 < 4; a3++) {
                c[a1][a2][a3] = 0.f;
            }
        }
    }

    int ra = tid >> 2;
    int cg = tid & 3;
    *(uint4*)&As[0][ra][cg * 8] = *(const uint4*)(g_xnb + (size_t)(m0 + ra) * 256 + cg * 8);
    *(uint4*)&As[0][64 + ra][cg * 8] = *(const uint4*)(g_xnb + (size_t)(m0 + 64 + ra) * 256 + cg * 8);
    *(uint4*)&Bs[0][ra][cg * 8] = *(const uint4*)(g_wqkvb + (size_t)(j0 + ra) * 256 + cg * 8);
    __syncthreads();

    int pg = 0;
    for (int ck = 0; ck < 8; ck++) {
        uint4 na0;
        uint4 na1;
        uint4 nb0;
        int ok = (ck < 7) ? 1 : 0;
        if (ok) {
            int kc = (ck + 1) * 32;
            na0 = *(const uint4*)(g_xnb + (size_t)(m0 + ra) * 256 + kc + cg * 8);
            na1 = *(const uint4*)(g_xnb + (size_t)(m0 + 64 + ra) * 256 + kc + cg * 8);
            nb0 = *(const uint4*)(g_wqkvb + (size_t)(j0 + ra) * 256 + kc + cg * 8);
        }
        #pragma unroll
        for (int ks = 0; ks < 2; ks++) {
            unsigned a[2][4];
            #pragma unroll
            for (int mt = 0; mt < 2; mt++) {
                ldsm4(a[mt][0], a[mt][1], a[mt][2], a[mt][3], s2u(&As[pg][wm + mt * 16 + (li & 15)][ks * 16 + (li >> 4) * 8]));
            }
            #pragma unroll
            for (int np = 0; np < 2; np++) {
                unsigned r0, r1, r2, r3;
                ldsm4(r0, r1, r2, r3, s2u(&Bs[pg][wn + np * 16 + (li & 15)][ks * 16 + (li >> 4) * 8]));
                #pragma unroll
                for (int mt = 0; mt < 2; mt++) {
                    mma16816(c[mt][2 * np], a[mt], r0, r2);
                    mma16816(c[mt][2 * np + 1], a[mt], r1, r3);
                }
            }
        }
        if (ok) {
            *(uint4*)&As[pg ^ 1][ra][cg * 8] = na0;
            *(uint4*)&As[pg ^ 1][64 + ra][cg * 8] = na1;
            *(uint4*)&Bs[pg ^ 1][ra][cg * 8] = nb0;
        }
        __syncthreads();
        pg ^= 1;
    }

    #pragma unroll
    for (int mt = 0; mt < 2; mt++) {
        int r = m0 + wm + mt * 16 + (li >> 2);
        #pragma unroll
        for (int nt = 0; nt < 4; nt++) {
            int jc = j0 + wn + nt * 8 + (li & 3) * 2;
            float b0 = bias[jc];
            float b1 = bias[jc + 1];
            float v0 = c[mt][nt][0] + b0;
            float v1 = c[mt][nt][1] + b1;
            float v2 = c[mt][nt][2] + b0;
            float v3 = c[mt][nt][3] + b1;
            if (jc < 256) {
                // q: prescale, e4m3
                *(unsigned short*)(g_q8 + (size_t)r * 256 + jc) = pack_e4(v0 * QSC, v1 * QSC);
                *(unsigned short*)(g_q8 + (size_t)(r + 8) * 256 + jc) = pack_e4(v2 * QSC, v3 * QSC);
            } else if (jc < 512) {
                // k: e4m3
                *(unsigned short*)(g_k8 + (size_t)r * 256 + jc - 256) = pack_e4(v0, v1);
                *(unsigned short*)(g_k8 + (size_t)(r + 8) * 256 + jc - 256) = pack_e4(v2, v3);
            } else {
                // v: bf16
                *(unsigned*)(g_vb + (size_t)r * 256 + jc - 512) = pack_bf(v0, v1);
                *(unsigned*)(g_vb + (size_t)(r + 8) * 256 + jc - 512) = pack_bf(v2, v3);
            }
        }
    }
}

// Kernel 3: flash attention, no-max softmax, M=32/warp, split-K=2,
// S=QK^T in e4m3 (m16n8k32, half the MMA instructions), PV in bf16.
__global__ __launch_bounds__(128, 5) void attn_kernel()
{
    __shared__ __align__(16) unsigned char Qs[128][48];
    __shared__ __align__(16) unsigned char Ks[2][64][48];
    __shared__ __align__(16) unsigned short Vs[2][64][40];
    int tid = threadIdx.x;
    int li = tid & 31;
    int wp = tid >> 5;          // 0..3, warp handles rows wp*32 .. wp*32+31
    int bid = blockIdx.x;
    int sk = bid & 1;           // k-split half
    int qt = (bid >> 1) & 31;
    int h = (bid >> 6) & 7;
    int bb = bid >> 9;
    int q0 = qt * 128;
    int kt0 = sk * 32;
    size_t bN = (size_t)bb * N_TOK;

    int rq = tid >> 1;          // 0..63
    int hf = tid & 1;
    int r4 = tid >> 2;          // 0..31
    int cg = tid & 3;
    // Q fp8: 128 rows x 32B
    *(uint4*)&Qs[rq][hf * 16] = *(const uint4*)(g_q8 + (bN + q0 + rq) * 256 + h * 32 + hf * 16);
    *(uint4*)&Qs[64 + rq][hf * 16] = *(const uint4*)(g_q8 + (bN + q0 + 64 + rq) * 256 + h * 32 + hf * 16);
    {
        size_t rowb = bN + (size_t)kt0 * 64;
        // K fp8 tile0: 64 rows x 32B
        *(uint4*)&Ks[0][rq][hf * 16] = *(const uint4*)(g_k8 + (rowb + rq) * 256 + h * 32 + hf * 16);
        // V bf16 tile0: 64 rows x 64B
        *(uint4*)&Vs[0][r4][cg * 8] = *(const uint4*)(g_vb + (rowb + r4) * 256 + h * 32 + cg * 8);
        *(uint4*)&Vs[0][32 + r4][cg * 8] = *(const uint4*)(g_vb + (rowb + 32 + r4) * 256 + h * 32 + cg * 8);
    }
    __syncthreads();

    // Q A-frags fp8: one x4 ldsm per 16-row block covers full k=32
    unsigned qa[2][4];
    #pragma unroll
    for (int mt = 0; mt < 2; mt++) {
        ldsm4(qa[mt][0], qa[mt][1], qa[mt][2], qa[mt][3], s2u(&Qs[wp * 32 + mt * 16 + (li & 15)][(li >> 4) * 16]));
    }

    float oacc[2][4][4];
    #pragma unroll
    for (int a1 = 0; a1 < 2; a1++) {
        #pragma unroll
        for (int a2 = 0; a2 < 4; a2++) {
            #pragma unroll
            for (int a3 = 0; a3 < 4; a3++) {
                oacc[a1][a2][a3] = 0.f;
            }
        }
    }
    float rl[4];
    #pragma unroll
    for (int a1 = 0; a1 < 4; a1++) {
        rl[a1] = 0.f;
    }

    for (int it = 0; it < 32; it++) {
        int cb = it & 1;
        uint4 kreg, vreg0, vreg1;
        int ok = (it + 1 < 32) ? 1 : 0;
        if (ok) {
            size_t rowb = bN + (size_t)(kt0 + it + 1) * 64;
            kreg = *(const uint4*)(g_k8 + (rowb + rq) * 256 + h * 32 + hf * 16);
            vreg0 = *(const uint4*)(g_vb + (rowb + r4) * 256 + h * 32 + cg * 8);
            vreg1 = *(const uint4*)(g_vb + (rowb + 32 + r4) * 256 + h * 32 + cg * 8);
        }

        // ---- S = Q K^T : 32x64 per warp, fp8 k32 MMAs ----
        float sacc[2][8][4];
        #pragma unroll
        for (int mt = 0; mt < 2; mt++) {
            #pragma unroll
            for (int nt = 0; nt < 8; nt++) {
                sacc[mt][nt][0] = 0.f;
                sacc[mt][nt][1] = 0.f;
                sacc[mt][nt][2] = 0.f;
                sacc[mt][nt][3] = 0.f;
            }
        }
        #pragma unroll
        for (int np = 0; np < 4; np++) {
            unsigned r0, r1, r2, r3;
            ldsm4(r0, r1, r2, r3, s2u(&Ks[cb][np * 16 + (li & 15)][(li >> 4) * 16]));
            #pragma unroll
            for (int mt = 0; mt < 2; mt++) {
                mma16832q(sacc[mt][2 * np], qa[mt], r0, r2);
                mma16832q(sacc[mt][2 * np + 1], qa[mt], r1, r3);
            }
        }

        // ---- p = exp2(s) directly (no max subtraction; s bounded) ----
        #pragma unroll
        for (int mt = 0; mt < 2; mt++) {
            #pragma unroll
            for (int nt = 0; nt < 8; nt++) {
                sacc[mt][nt][0] = ex2f(sacc[mt][nt][0]);
                sacc[mt][nt][1] = ex2f(sacc[mt][nt][1]);
                sacc[mt][nt][2] = ex2f(sacc[mt][nt][2]);
                sacc[mt][nt][3] = ex2f(sacc[mt][nt][3]);
                rl[mt * 2] += sacc[mt][nt][0] + sacc[mt][nt][1];
                rl[mt * 2 + 1] += sacc[mt][nt][2] + sacc[mt][nt][3];
            }
        }

        // ---- O += P V : repack S C-frags as bf16 A-frags ----
        #pragma unroll
        for (int j = 0; j < 4; j++) {
            unsigned pa[2][4];
            #pragma unroll
            for (int mt = 0; mt < 2; mt++) {
                pa[mt][0] = pack_bf(sacc[mt][2 * j][0], sacc[mt][2 * j][1]);
                pa[mt][1] = pack_bf(sacc[mt][2 * j][2], sacc[mt][2 * j][3]);
                pa[mt][2] = pack_bf(sacc[mt][2 * j + 1][0], sacc[mt][2 * j + 1][1]);
                pa[mt][3] = pack_bf(sacc[mt][2 * j + 1][2], sacc[mt][2 * j + 1][3]);
            }
            unsigned r0, r1, r2, r3;
            ldsm4t(r0, r1, r2, r3, s2u(&Vs[cb][j * 16 + (li & 15)][(li >> 4) * 8]));
            #pragma unroll
            for (int mt = 0; mt < 2; mt++) {
                mma16816(oacc[mt][0], pa[mt], r0, r1);
                mma16816(oacc[mt][1], pa[mt], r2, r3);
            }
            ldsm4t(r0, r1, r2, r3, s2u(&Vs[cb][j * 16 + (li & 15)][16 + (li >> 4) * 8]));
            #pragma unroll
            for (int mt = 0; mt < 2; mt++) {
                mma16816(oacc[mt][2], pa[mt], r0, r1);
                mma16816(oacc[mt][3], pa[mt], r2, r3);
            }
        }

        if (ok) {
            *(uint4*)&Ks[cb ^ 1][rq][hf * 16] = kreg;
            *(uint4*)&Vs[cb ^ 1][r4][cg * 8] = vreg0;
            *(uint4*)&Vs[cb ^ 1][32 + r4][cg * 8] = vreg1;
        }
        __syncthreads();
    }

    // epilogue: reduce row sums across quads, store un-normalized fp32 partials
    size_t obase = (size_t)(sk * 2 + bb) * N_TOK;
    int lbase = ((sk * 2 + bb) * 8 + h) * N_TOK;
    #pragma unroll
    for (int mt = 0; mt < 2; mt++) {
        float s0 = rl[mt * 2];
        float s1 = rl[mt * 2 + 1];
        s0 += __shfl_xor_sync(0xffffffffu, s0, 1);
        s0 += __shfl_xor_sync(0xffffffffu, s0, 2);
        s1 += __shfl_xor_sync(0xffffffffu, s1, 1);
        s1 += __shfl_xor_sync(0xffffffffu, s1, 2);
        int rg = q0 + wp * 32 + mt * 16 + (li >> 2);
        if ((li & 3) == 0) {
            g_lpart[lbase + rg] = s0;
            g_lpart[lbase + rg + 8] = s1;
        }
        #pragma unroll
        for (int nt = 0; nt < 4; nt++) {
            int col = h * 32 + nt * 8 + (li & 3) * 2;
            float2 v0;
            v0.x = oacc[mt][nt][0];
            v0.y = oacc[mt][nt][1];
            float2 v1;
            v1.x = oacc[mt][nt][2];
            v1.y = oacc[mt][nt][3];
            *(float2*)(g_opart + (obase + rg) * 256 + col) = v0;
            *(float2*)(g_opart + (obase + rg + 8) * 256 + col) = v1;
        }
    }
}

// Kernel 3b: merge split-K partials -> bf16 attention output
__global__ __launch_bounds__(256) void merge_kernel()
{
    int idx = (blockIdx.x * 256 + threadIdx.x) * 4;
    int r = idx >> 8;
    int col = idx & 255;
    int bb = r >> 12;
    int row = r & 4095;
    int h = col >> 5;
    float l = g_lpart[(bb * 8 + h) * N_TOK + row] + g_lpart[((2 + bb) * 8 + h) * N_TOK + row];
    float inv = 1.0f / l;
    float4 o0 = *(const float4*)(g_opart + (size_t)r * 256 + col);
    float4 o1 = *(const float4*)(g_opart + (size_t)(r + 8192) * 256 + col);
    uint2 pk;
    pk.x = pack_bf((o0.x + o1.x) * inv, (o0.y + o1.y) * inv);
    pk.y = pack_bf((o0.z + o1.z) * inv, (o0.w + o1.w) * inv);
    *(uint2*)(g_attb + (size_t)r * 256 + col) = pk;
}

// Kernel 4: proj GEMM bf16 + gamma residual, (B,N,C)->(B,C,N) via smem
#define PROJ_SMEM_BYTES 33024

__global__ __launch_bounds__(256) void proj_kernel(const float* __restrict__ bias, const float* __restrict__ gamma, const float* __restrict__ x, float* __restrict__ out)
{
    __shared__ __align__(16) char smraw[PROJ_SMEM_BYTES];
    unsigned short (*As)[128][40] = (unsigned short (*)[128][40])(smraw);
    unsigned short (*Bs)[64][40] = (unsigned short (*)[64][40])(smraw + 20480);
    float (*Cs)[129] = (float (*)[129])(smraw);

    int tid = threadIdx.x;
    int li = tid & 31;
    int wp = tid >> 5;
    int m0 = blockIdx.x * 128;
    int j0 = blockIdx.y * 64;
    int wm = (wp >> 1) * 32;
    int wn = (wp & 1) * 32;
    float c[2][4][4];
    #pragma unroll
    for (int a1 = 0; a1 < 2; a1++) {
        #pragma unroll
        for (int a2 = 0; a2 < 4; a2++) {
            #pragma unroll
            for (int a3 = 0; a3 < 4; a3++) {
                c[a1][a2][a3] = 0.f;
            }
        }
    }
    int ra = tid >> 2;
    int cg = tid & 3;

    *(uint4*)&As[0][ra][cg * 8] = *(const uint4*)(g_attb + (size_t)(m0 + ra) * 256 + cg * 8);
    *(uint4*)&As[0][64 + ra][cg * 8] = *(const uint4*)(g_attb + (size_t)(m0 + 64 + ra) * 256 + cg * 8);
    *(uint4*)&Bs[0][ra][cg * 8] = *(const uint4*)(g_wprojb + (size_t)(j0 + ra) * 256 + cg * 8);
    __syncthreads();

    int pg = 0;
    for (int ck = 0; ck < 8; ck++) {
        uint4 na0;
        uint4 na1;
        uint4 nb0;
        int ok = (ck < 7) ? 1 : 0;
        if (ok) {
            int kc = (ck + 1) * 32;
            na0 = *(const uint4*)(g_attb + (size_t)(m0 + ra) * 256 + kc + cg * 8);
            na1 = *(const uint4*)(g_attb + (size_t)(m0 + 64 + ra) * 256 + kc + cg * 8);
            nb0 = *(const uint4*)(g_wprojb + (size_t)(j0 + ra) * 256 + kc + cg * 8);
        }
        #pragma unroll
        for (int ks = 0; ks < 2; ks++) {
            unsigned a[2][4];
            #pragma unroll
            for (int mt = 0; mt < 2; mt++) {
                ldsm4(a[mt][0], a[mt][1], a[mt][2], a[mt][3], s2u(&As[pg][wm + mt * 16 + (li & 15)][ks * 16 + (li >> 4) * 8]));
            }
            #pragma unroll
            for (int np = 0; np < 2; np++) {
                unsigned r0, r1, r2, r3;
                ldsm4(r0, r1, r2, r3, s2u(&Bs[pg][wn + np * 16 + (li & 15)][ks * 16 + (li >> 4) * 8]));
                #pragma unroll
                for (int mt = 0; mt < 2; mt++) {
                    mma16816(c[mt][2 * np], a[mt], r0, r2);
                    mma16816(c[mt][2 * np + 1], a[mt], r1, r3);
                }
            }
        }
        if (ok) {
            *(uint4*)&As[pg ^ 1][ra][cg * 8] = na0;
            *(uint4*)&As[pg ^ 1][64 + ra][cg * 8] = na1;
            *(uint4*)&Bs[pg ^ 1][ra][cg * 8] = nb0;
        }
        __syncthreads();
        pg ^= 1;
    }

    __syncthreads();
    #pragma unroll
    for (int mt = 0; mt < 2; mt++) {
        int rl = wm + mt * 16 + (li >> 2);
        #pragma unroll
        for (int nt = 0; nt < 4; nt++) {
            int cl = wn + nt * 8 + (li & 3) * 2;
            float b0 = bias[j0 + cl];
            float b1 = bias[j0 + cl + 1];
            Cs[cl][rl] = c[mt][nt][0] + b0;
            Cs[cl + 1][rl] = c[mt][nt][1] + b1;
            Cs[cl][rl + 8] = c[mt][nt][2] + b0;
            Cs[cl + 1][rl + 8] = c[mt][nt][3] + b1;
        }
    }
    __syncthreads();

    float g0 = gamma[0];
    int bb = m0 >> 12;
    int n0 = m0 & 4095;
    #pragma unroll
    for (int p = 0; p < 32; p++) {
        int idx = p * 256 + tid;
        int cl = idx >> 7;
        int rl = idx & 127;
        size_t gi = (size_t)(bb * 256 + j0 + cl) * 4096 + n0 + rl;
        out[gi] = g0 * Cs[cl][rl] + x[gi];
    }
}

extern "C" void kernel_launch(void* const* d_in, const int* in_sizes, int n_in, void* d_out, int out_size)
{
    const float* x = (const float*)d_in[0];
    const float* norm_w = (const float*)d_in[1];
    const float* norm_b = (const float*)d_in[2];
    const float* qkv_w = (const float*)d_in[3];
    const float* qkv_b = (const float*)d_in[4];
    const float* proj_w = (const float*)d_in[5];
    const float* proj_b = (const float*)d_in[6];
    const float* gamma = (const float*)d_in[7];
    float* out = (float*)d_out;

    convw_kernel<<<512, 256>>>(qkv_w, proj_w);
    ln_kernel<<<256, 256>>>(x, norm_w, norm_b);
    qkv_gemm_kernel<<<dim3(64, 12), 256>>>(qkv_b);
    attn_kernel<<<1024, 128>>>();
    merge_kernel<<<2048, 256>>>();
    proj_kernel<<<dim3(64, 4), 256>>>(proj_b, gamma, x, out);
}